// round 3
// baseline (speedup 1.0000x reference)
#include <cuda_runtime.h>
#include <cstdint>

#define NPMAX 100000
#define NCC   80
#define NGMAX 300
#define EPSF  1e-7f
#define C_V   0.4052847345693511f   // 4/pi^2

// ---- scratch (static device arrays; no runtime allocation) ----
__device__ float d_probT[(size_t)NCC * NPMAX];   // 32 MB, [class][pred]
__device__ float d_px1[NPMAX], d_py1[NPMAX], d_px2[NPMAX], d_py2[NPMAX];
__device__ float d_parea[NPMAX], d_patan[NPMAX], d_pcx[NPMAX], d_pcy[NPMAX];
__device__ float d_gx1[NGMAX], d_gy1[NGMAX], d_gx2[NGMAX], d_gy2[NGMAX];
__device__ float d_garea[NGMAX], d_gatan[NGMAX], d_gcx[NGMAX], d_gcy[NGMAX];
__device__ int   d_gcls[NGMAX];

// ---------------- per-prediction box prep ----------------
__global__ void prep_pred_kernel(const float* __restrict__ preds, int NP) {
    int p = blockIdx.x * blockDim.x + threadIdx.x;
    if (p >= NP) return;
    const float* r = preds + (size_t)p * (5 + NCC);
    float xc = r[0], yc = r[1], w = r[2], h = r[3];
    float x1 = xc - 0.5f * w, y1 = yc - 0.5f * h;
    float x2 = xc + 0.5f * w, y2 = yc + 0.5f * h;
    d_px1[p] = x1; d_py1[p] = y1; d_px2[p] = x2; d_py2[p] = y2;
    d_parea[p] = fmaxf(x2 - x1, 0.f) * fmaxf(y2 - y1, 0.f);
    float wp = fmaxf(x2 - x1, EPSF), hp = fmaxf(y2 - y1, EPSF);
    d_patan[p] = atanf(wp / hp);
    d_pcx[p] = 0.5f * (x1 + x2);
    d_pcy[p] = 0.5f * (y1 + y2);
}

// ---------------- per-gt prep ----------------
__global__ void prep_gt_kernel(const float* __restrict__ gt_boxes,
                               const int* __restrict__ gt_classes, int NG) {
    int g = blockIdx.x * blockDim.x + threadIdx.x;
    if (g >= NG) return;
    float x1 = gt_boxes[g * 4 + 0], y1 = gt_boxes[g * 4 + 1];
    float x2 = gt_boxes[g * 4 + 2], y2 = gt_boxes[g * 4 + 3];
    d_gx1[g] = x1; d_gy1[g] = y1; d_gx2[g] = x2; d_gy2[g] = y2;
    d_garea[g] = fmaxf(x2 - x1, 0.f) * fmaxf(y2 - y1, 0.f);
    float wg = fmaxf(x2 - x1, EPSF), hg = fmaxf(y2 - y1, EPSF);
    d_gatan[g] = atanf(wg / hg);
    d_gcx[g] = 0.5f * (x1 + x2);
    d_gcy[g] = 0.5f * (y1 + y2);
    d_gcls[g] = gt_classes[g];
}

// ---------------- sigmoid + transpose: probT[c][p] ----------------
// Block = 256 threads, handles 64 preds x 80 classes via padded smem tile.
__global__ void sig_transpose_kernel(const float* __restrict__ preds, int NP) {
    __shared__ float tile[64][NCC + 1];  // +1 pad -> conflict-free transposed reads
    int p0 = blockIdx.x * 64;
    int nblk = min(64, NP - p0);
    // load (coalesced along class dim), apply sigmoid
    for (int i = threadIdx.x; i < 64 * NCC; i += blockDim.x) {
        int pp = i / NCC, cc = i - pp * NCC;
        float v = 0.f;
        if (pp < nblk) v = preds[(size_t)(p0 + pp) * (5 + NCC) + 5 + cc];
        tile[pp][cc] = 1.0f / (1.0f + __expf(-v));
    }
    __syncthreads();
    // store transposed (coalesced along pred dim)
    for (int i = threadIdx.x; i < NCC * 64; i += blockDim.x) {
        int cc = i / 64, pp = i - cc * 64;
        if (pp < nblk)
            d_probT[(size_t)cc * NP + p0 + pp] = tile[pp][cc];
    }
}

// ---------------- cost matrix ----------------
__global__ void cost_kernel(float* __restrict__ cost, int NP, int NG) {
    __shared__ float sx1[NGMAX], sy1[NGMAX], sx2[NGMAX], sy2[NGMAX];
    __shared__ float sar[NGMAX], sat[NGMAX], scx[NGMAX], scy[NGMAX];
    __shared__ int   scl[NGMAX];
    for (int g = threadIdx.x; g < NG; g += blockDim.x) {
        sx1[g] = d_gx1[g]; sy1[g] = d_gy1[g]; sx2[g] = d_gx2[g]; sy2[g] = d_gy2[g];
        sar[g] = d_garea[g]; sat[g] = d_gatan[g]; scx[g] = d_gcx[g]; scy[g] = d_gcy[g];
        scl[g] = d_gcls[g];
    }
    __syncthreads();
    int p = blockIdx.x * blockDim.x + threadIdx.x;
    if (p >= NP) return;

    float px1 = d_px1[p], py1 = d_py1[p], px2 = d_px2[p], py2 = d_py2[p];
    float parea = d_parea[p], patan = d_patan[p], pcx = d_pcx[p], pcy = d_pcy[p];

    for (int g = 0; g < NG; ++g) {
        float gx1 = sx1[g], gy1 = sy1[g], gx2 = sx2[g], gy2 = sy2[g];
        float ix1 = fmaxf(px1, gx1), iy1 = fmaxf(py1, gy1);
        float ix2 = fminf(px2, gx2), iy2 = fminf(py2, gy2);
        float inter = fmaxf(ix2 - ix1, 0.f) * fmaxf(iy2 - iy1, 0.f);
        float uni = parea + sar[g] - inter + EPSF;
        float iou = __fdividef(inter, uni);
        float dx = pcx - scx[g], dy = pcy - scy[g];
        float d2 = dx * dx + dy * dy;
        float cw = fmaxf(fmaxf(px2, gx2) - fminf(px1, gx1), EPSF);
        float ch = fmaxf(fmaxf(py2, gy2) - fminf(py1, gy1), EPSF);
        float c2 = cw * cw + ch * ch + EPSF;
        float dat = sat[g] - patan;
        float v = C_V * dat * dat;
        float alpha = __fdividef(v, 1.0f - iou + v + EPSF);
        float ciou = iou - __fdividef(d2, c2) - alpha * v;
        float cls = d_probT[(size_t)scl[g] * NP + p];
        float c = 0.75f * (1.0f - cls) + 1.0f * (1.0f - fminf(fmaxf(ciou, 0.f), 1.f));
        cost[(size_t)g * NP + p] = c;
    }
}

// ---------------- per-gt exact top-K (K<=10) ----------------
// key = (float_bits(cost) << 32) | p  -> min-order == top_k(-cost) with
// ties broken by lower index, exactly matching jax.lax.top_k.
#define TKT 256
__global__ void topk_kernel(const float* __restrict__ cost, float* __restrict__ out,
                            int NP, int NG,
                            const int* __restrict__ epoch_p,
                            const int* __restrict__ tot_p) {
    int g = blockIdx.x;
    int ep = epoch_p[0];
    int te = tot_p[0];
    float t = (float)ep / (float)max(1, te - 1);
    int K = (int)rintf(10.0f - 9.0f * t);
    K = min(10, max(1, K));
    K = min(K, NP);

    unsigned long long loc[10];
#pragma unroll
    for (int i = 0; i < 10; ++i) loc[i] = ~0ULL;

    const float* row = cost + (size_t)g * NP;
    for (int p = threadIdx.x; p < NP; p += TKT) {
        unsigned long long key =
            ((unsigned long long)__float_as_uint(row[p]) << 32) | (unsigned)p;
        if (key < loc[9]) {
            int j = 9;
            while (j > 0 && loc[j - 1] > key) { loc[j] = loc[j - 1]; --j; }
            loc[j] = key;
        }
    }

    __shared__ unsigned long long lists[TKT][10];
    __shared__ unsigned long long red[TKT];
    __shared__ int head[TKT];
#pragma unroll
    for (int i = 0; i < 10; ++i) lists[threadIdx.x][i] = loc[i];
    head[threadIdx.x] = 0;
    __syncthreads();

    for (int r = 0; r < K; ++r) {
        unsigned long long cand = lists[threadIdx.x][head[threadIdx.x]];
        red[threadIdx.x] = cand;
        __syncthreads();
        for (int s = TKT / 2; s > 0; s >>= 1) {
            if (threadIdx.x < s)
                red[threadIdx.x] = min(red[threadIdx.x], red[threadIdx.x + s]);
            __syncthreads();
        }
        unsigned long long win = red[0];
        if (cand == win) head[threadIdx.x]++;   // key unique (contains p)
        if (threadIdx.x == 0) {
            int p = (int)(unsigned)(win & 0xffffffffULL);
            size_t base = (size_t)NG * NP + 2 * ((size_t)g * K + r);
            out[base + 0] = (float)p;
            out[base + 1] = (float)g;
        }
        __syncthreads();
    }
}

extern "C" void kernel_launch(void* const* d_in, const int* in_sizes, int n_in,
                              void* d_out, int out_size) {
    const float* preds      = (const float*)d_in[0];
    const float* gt_boxes   = (const float*)d_in[1];
    const int*   gt_classes = (const int*)d_in[2];
    const int*   epoch      = (const int*)d_in[3];
    const int*   tot        = (const int*)d_in[4];

    int NP = in_sizes[0] / (5 + NCC);
    int NG = in_sizes[2];
    float* out = (float*)d_out;

    prep_pred_kernel<<<(NP + 255) / 256, 256>>>(preds, NP);
    prep_gt_kernel<<<(NG + 255) / 256, 256>>>(gt_boxes, gt_classes, NG);
    sig_transpose_kernel<<<(NP + 63) / 64, 256>>>(preds, NP);
    cost_kernel<<<(NP + 255) / 256, 256>>>(out, NP, NG);
    topk_kernel<<<NG, TKT>>>(out, out, NP, NG, epoch, tot);
}

// round 4
// speedup vs baseline: 1.0061x; 1.0061x over previous
#include <cuda_runtime.h>
#include <cstdint>

#define NPMAX 100000
#define NCC   80
#define NGMAX 300
#define EPSF  1e-7f
#define C_V   0.4052847345693511f   // 4/pi^2

// ---- scratch (static device arrays; no runtime allocation) ----
__device__ float d_probT[(size_t)NCC * NPMAX];   // 32 MB, [class][pred]
__device__ float d_px1[NPMAX], d_py1[NPMAX], d_px2[NPMAX], d_py2[NPMAX];
__device__ float d_parea[NPMAX], d_patan[NPMAX], d_pcx[NPMAX], d_pcy[NPMAX];
__device__ float d_gx1[NGMAX], d_gy1[NGMAX], d_gx2[NGMAX], d_gy2[NGMAX];
__device__ float d_garea[NGMAX], d_gatan[NGMAX], d_gcx[NGMAX], d_gcy[NGMAX];
__device__ int   d_gcls[NGMAX];

// ---------------- per-prediction box prep ----------------
__global__ void prep_pred_kernel(const float* __restrict__ preds, int NP) {
    int p = blockIdx.x * blockDim.x + threadIdx.x;
    if (p >= NP) return;
    const float* r = preds + (size_t)p * (5 + NCC);
    float xc = r[0], yc = r[1], w = r[2], h = r[3];
    float x1 = xc - 0.5f * w, y1 = yc - 0.5f * h;
    float x2 = xc + 0.5f * w, y2 = yc + 0.5f * h;
    d_px1[p] = x1; d_py1[p] = y1; d_px2[p] = x2; d_py2[p] = y2;
    d_parea[p] = fmaxf(x2 - x1, 0.f) * fmaxf(y2 - y1, 0.f);
    float wp = fmaxf(x2 - x1, EPSF), hp = fmaxf(y2 - y1, EPSF);
    d_patan[p] = atanf(wp / hp);
    d_pcx[p] = 0.5f * (x1 + x2);
    d_pcy[p] = 0.5f * (y1 + y2);
}

// ---------------- per-gt prep ----------------
__global__ void prep_gt_kernel(const float* __restrict__ gt_boxes,
                               const int* __restrict__ gt_classes, int NG) {
    int g = blockIdx.x * blockDim.x + threadIdx.x;
    if (g >= NG) return;
    float x1 = gt_boxes[g * 4 + 0], y1 = gt_boxes[g * 4 + 1];
    float x2 = gt_boxes[g * 4 + 2], y2 = gt_boxes[g * 4 + 3];
    d_gx1[g] = x1; d_gy1[g] = y1; d_gx2[g] = x2; d_gy2[g] = y2;
    d_garea[g] = fmaxf(x2 - x1, 0.f) * fmaxf(y2 - y1, 0.f);
    float wg = fmaxf(x2 - x1, EPSF), hg = fmaxf(y2 - y1, EPSF);
    d_gatan[g] = atanf(wg / hg);
    d_gcx[g] = 0.5f * (x1 + x2);
    d_gcy[g] = 0.5f * (y1 + y2);
    d_gcls[g] = gt_classes[g];
}

// ---------------- sigmoid + transpose: probT[c][p] ----------------
// Block = 256 threads, handles 64 preds x 80 classes via padded smem tile.
__global__ void sig_transpose_kernel(const float* __restrict__ preds, int NP) {
    __shared__ float tile[64][NCC + 1];  // +1 pad -> conflict-free transposed reads
    int p0 = blockIdx.x * 64;
    int nblk = min(64, NP - p0);
    // load (coalesced along class dim), apply sigmoid
    for (int i = threadIdx.x; i < 64 * NCC; i += blockDim.x) {
        int pp = i / NCC, cc = i - pp * NCC;
        float v = 0.f;
        if (pp < nblk) v = preds[(size_t)(p0 + pp) * (5 + NCC) + 5 + cc];
        tile[pp][cc] = 1.0f / (1.0f + __expf(-v));
    }
    __syncthreads();
    // store transposed (coalesced along pred dim)
    for (int i = threadIdx.x; i < NCC * 64; i += blockDim.x) {
        int cc = i / 64, pp = i - cc * 64;
        if (pp < nblk)
            d_probT[(size_t)cc * NP + p0 + pp] = tile[pp][cc];
    }
}

// ---------------- cost matrix ----------------
__global__ void cost_kernel(float* __restrict__ cost, int NP, int NG) {
    __shared__ float sx1[NGMAX], sy1[NGMAX], sx2[NGMAX], sy2[NGMAX];
    __shared__ float sar[NGMAX], sat[NGMAX], scx[NGMAX], scy[NGMAX];
    __shared__ int   scl[NGMAX];
    for (int g = threadIdx.x; g < NG; g += blockDim.x) {
        sx1[g] = d_gx1[g]; sy1[g] = d_gy1[g]; sx2[g] = d_gx2[g]; sy2[g] = d_gy2[g];
        sar[g] = d_garea[g]; sat[g] = d_gatan[g]; scx[g] = d_gcx[g]; scy[g] = d_gcy[g];
        scl[g] = d_gcls[g];
    }
    __syncthreads();
    int p = blockIdx.x * blockDim.x + threadIdx.x;
    if (p >= NP) return;

    float px1 = d_px1[p], py1 = d_py1[p], px2 = d_px2[p], py2 = d_py2[p];
    float parea = d_parea[p], patan = d_patan[p], pcx = d_pcx[p], pcy = d_pcy[p];

    for (int g = 0; g < NG; ++g) {
        float gx1 = sx1[g], gy1 = sy1[g], gx2 = sx2[g], gy2 = sy2[g];
        float ix1 = fmaxf(px1, gx1), iy1 = fmaxf(py1, gy1);
        float ix2 = fminf(px2, gx2), iy2 = fminf(py2, gy2);
        float inter = fmaxf(ix2 - ix1, 0.f) * fmaxf(iy2 - iy1, 0.f);
        float uni = parea + sar[g] - inter + EPSF;
        float iou = __fdividef(inter, uni);
        float dx = pcx - scx[g], dy = pcy - scy[g];
        float d2 = dx * dx + dy * dy;
        float cw = fmaxf(fmaxf(px2, gx2) - fminf(px1, gx1), EPSF);
        float ch = fmaxf(fmaxf(py2, gy2) - fminf(py1, gy1), EPSF);
        float c2 = cw * cw + ch * ch + EPSF;
        float dat = sat[g] - patan;
        float v = C_V * dat * dat;
        float alpha = __fdividef(v, 1.0f - iou + v + EPSF);
        float ciou = iou - __fdividef(d2, c2) - alpha * v;
        float cls = d_probT[(size_t)scl[g] * NP + p];
        float c = 0.75f * (1.0f - cls) + 1.0f * (1.0f - fminf(fmaxf(ciou, 0.f), 1.f));
        cost[(size_t)g * NP + p] = c;
    }
}

// ---------------- per-gt exact top-K (K<=10) ----------------
// key = (float_bits(cost) << 32) | p  -> min-order == top_k(-cost) with
// ties broken by lower index, exactly matching jax.lax.top_k.
#define TKT 256
__global__ void topk_kernel(const float* __restrict__ cost, float* __restrict__ out,
                            int NP, int NG,
                            const int* __restrict__ epoch_p,
                            const int* __restrict__ tot_p) {
    int g = blockIdx.x;
    int ep = epoch_p[0];
    int te = tot_p[0];
    float t = (float)ep / (float)max(1, te - 1);
    int K = (int)rintf(10.0f - 9.0f * t);
    K = min(10, max(1, K));
    K = min(K, NP);

    unsigned long long loc[10];
#pragma unroll
    for (int i = 0; i < 10; ++i) loc[i] = ~0ULL;

    const float* row = cost + (size_t)g * NP;
    for (int p = threadIdx.x; p < NP; p += TKT) {
        unsigned long long key =
            ((unsigned long long)__float_as_uint(row[p]) << 32) | (unsigned)p;
        if (key < loc[9]) {
            int j = 9;
            while (j > 0 && loc[j - 1] > key) { loc[j] = loc[j - 1]; --j; }
            loc[j] = key;
        }
    }

    __shared__ unsigned long long lists[TKT][10];
    __shared__ unsigned long long red[TKT];
    __shared__ int head[TKT];
#pragma unroll
    for (int i = 0; i < 10; ++i) lists[threadIdx.x][i] = loc[i];
    head[threadIdx.x] = 0;
    __syncthreads();

    for (int r = 0; r < K; ++r) {
        unsigned long long cand = lists[threadIdx.x][head[threadIdx.x]];
        red[threadIdx.x] = cand;
        __syncthreads();
        for (int s = TKT / 2; s > 0; s >>= 1) {
            if (threadIdx.x < s)
                red[threadIdx.x] = min(red[threadIdx.x], red[threadIdx.x + s]);
            __syncthreads();
        }
        unsigned long long win = red[0];
        if (cand == win) head[threadIdx.x]++;   // key unique (contains p)
        if (threadIdx.x == 0) {
            int p = (int)(unsigned)(win & 0xffffffffULL);
            size_t base = (size_t)NG * NP + 2 * ((size_t)g * K + r);
            out[base + 0] = (float)p;
            out[base + 1] = (float)g;
        }
        __syncthreads();
    }
}

extern "C" void kernel_launch(void* const* d_in, const int* in_sizes, int n_in,
                              void* d_out, int out_size) {
    const float* preds      = (const float*)d_in[0];
    const float* gt_boxes   = (const float*)d_in[1];
    const int*   gt_classes = (const int*)d_in[2];
    const int*   epoch      = (const int*)d_in[3];
    const int*   tot        = (const int*)d_in[4];

    int NP = in_sizes[0] / (5 + NCC);
    int NG = in_sizes[2];
    float* out = (float*)d_out;

    prep_pred_kernel<<<(NP + 255) / 256, 256>>>(preds, NP);
    prep_gt_kernel<<<(NG + 255) / 256, 256>>>(gt_boxes, gt_classes, NG);
    sig_transpose_kernel<<<(NP + 63) / 64, 256>>>(preds, NP);
    cost_kernel<<<(NP + 255) / 256, 256>>>(out, NP, NG);
    topk_kernel<<<NG, TKT>>>(out, out, NP, NG, epoch, tot);
}

// round 5
// speedup vs baseline: 1.4335x; 1.4248x over previous
#include <cuda_runtime.h>
#include <cstdint>

#define NPMAX 100000
#define NCC   80
#define NGMAX 300
#define EPSF  1e-7f
#define C_V   0.4052847345693511f   // 4/pi^2
#define CH    20                    // top-k phase-1 chunks per row
#define GSPAN 64                    // g-rows per cost block

// ---- scratch (static device arrays; no runtime allocation) ----
__device__ float d_probT[(size_t)NCC * NPMAX];   // 32 MB, [class][pred]
__device__ float d_px1[NPMAX], d_py1[NPMAX], d_px2[NPMAX], d_py2[NPMAX];
__device__ float d_parea[NPMAX], d_patan[NPMAX], d_pcx[NPMAX], d_pcy[NPMAX];
__device__ float d_gx1[NGMAX], d_gy1[NGMAX], d_gx2[NGMAX], d_gy2[NGMAX];
__device__ float d_garea[NGMAX], d_gatan[NGMAX], d_gcx[NGMAX], d_gcy[NGMAX];
__device__ int   d_gcls[NGMAX];
__device__ unsigned long long d_cand[(size_t)NGMAX * CH * 10];  // per-chunk top-10

// ---------------- helpers: register-resident top-10 ----------------
// t[0..9] unsorted, curmax = max(t). All indices static after unroll -> stays
// in registers (the R0-R4 topk's dynamic-index insertion sort spilled to local).
__device__ __forceinline__ void top10_insert(unsigned long long (&t)[10],
                                             unsigned long long& curmax,
                                             unsigned long long key) {
    if (key < curmax) {
        bool done = false;
#pragma unroll
        for (int i = 0; i < 10; ++i)
            if (!done && t[i] == curmax) { t[i] = key; done = true; }
        unsigned long long m = t[0];
#pragma unroll
        for (int i = 1; i < 10; ++i) m = t[i] > m ? t[i] : m;
        curmax = m;
    }
}

__device__ __forceinline__ unsigned long long top10_min(const unsigned long long (&t)[10]) {
    unsigned long long m = t[0];
#pragma unroll
    for (int i = 1; i < 10; ++i) m = t[i] < m ? t[i] : m;
    return m;
}

__device__ __forceinline__ void top10_kill(unsigned long long (&t)[10],
                                           unsigned long long v) {
    bool done = false;
#pragma unroll
    for (int i = 0; i < 10; ++i)
        if (!done && t[i] == v) { t[i] = ~0ULL; done = true; }
}

__device__ __forceinline__ unsigned long long warp_min_u64(unsigned long long v) {
#pragma unroll
    for (int s = 16; s > 0; s >>= 1) {
        unsigned long long o = __shfl_xor_sync(0xffffffffu, v, s);
        v = o < v ? o : v;
    }
    return v;
}

// ---------------- per-prediction box prep ----------------
__global__ void prep_pred_kernel(const float* __restrict__ preds, int NP) {
    int p = blockIdx.x * blockDim.x + threadIdx.x;
    if (p >= NP) return;
    const float* r = preds + (size_t)p * (5 + NCC);
    float xc = r[0], yc = r[1], w = r[2], h = r[3];
    float x1 = xc - 0.5f * w, y1 = yc - 0.5f * h;
    float x2 = xc + 0.5f * w, y2 = yc + 0.5f * h;
    d_px1[p] = x1; d_py1[p] = y1; d_px2[p] = x2; d_py2[p] = y2;
    d_parea[p] = fmaxf(x2 - x1, 0.f) * fmaxf(y2 - y1, 0.f);
    float wp = fmaxf(x2 - x1, EPSF), hp = fmaxf(y2 - y1, EPSF);
    d_patan[p] = atanf(wp / hp);
    d_pcx[p] = 0.5f * (x1 + x2);
    d_pcy[p] = 0.5f * (y1 + y2);
}

// ---------------- per-gt prep ----------------
__global__ void prep_gt_kernel(const float* __restrict__ gt_boxes,
                               const int* __restrict__ gt_classes, int NG) {
    int g = blockIdx.x * blockDim.x + threadIdx.x;
    if (g >= NG) return;
    float x1 = gt_boxes[g * 4 + 0], y1 = gt_boxes[g * 4 + 1];
    float x2 = gt_boxes[g * 4 + 2], y2 = gt_boxes[g * 4 + 3];
    d_gx1[g] = x1; d_gy1[g] = y1; d_gx2[g] = x2; d_gy2[g] = y2;
    d_garea[g] = fmaxf(x2 - x1, 0.f) * fmaxf(y2 - y1, 0.f);
    float wg = fmaxf(x2 - x1, EPSF), hg = fmaxf(y2 - y1, EPSF);
    d_gatan[g] = atanf(wg / hg);
    d_gcx[g] = 0.5f * (x1 + x2);
    d_gcy[g] = 0.5f * (y1 + y2);
    d_gcls[g] = gt_classes[g];
}

// ---------------- sigmoid + transpose: probT[c][p] ----------------
__global__ void sig_transpose_kernel(const float* __restrict__ preds, int NP) {
    __shared__ float tile[64][NCC + 1];
    int p0 = blockIdx.x * 64;
    int nblk = min(64, NP - p0);
    for (int i = threadIdx.x; i < 64 * NCC; i += blockDim.x) {
        int pp = i / NCC, cc = i - pp * NCC;
        float v = 0.f;
        if (pp < nblk) v = preds[(size_t)(p0 + pp) * (5 + NCC) + 5 + cc];
        tile[pp][cc] = 1.0f / (1.0f + __expf(-v));
    }
    __syncthreads();
    for (int i = threadIdx.x; i < NCC * 64; i += blockDim.x) {
        int cc = i / 64, pp = i - cc * 64;
        if (pp < nblk)
            d_probT[(size_t)cc * NP + p0 + pp] = tile[pp][cc];
    }
}

// ---------------- cost matrix (g-split for occupancy) ----------------
__global__ void cost_kernel(float* __restrict__ cost, int NP, int NG) {
    __shared__ float sx1[GSPAN], sy1[GSPAN], sx2[GSPAN], sy2[GSPAN];
    __shared__ float sar[GSPAN], sat[GSPAN], scx[GSPAN], scy[GSPAN];
    __shared__ int   scl[GSPAN];
    int g0 = blockIdx.y * GSPAN;
    int gn = min(GSPAN, NG - g0);
    for (int g = threadIdx.x; g < gn; g += blockDim.x) {
        int gg = g0 + g;
        sx1[g] = d_gx1[gg]; sy1[g] = d_gy1[gg]; sx2[g] = d_gx2[gg]; sy2[g] = d_gy2[gg];
        sar[g] = d_garea[gg]; sat[g] = d_gatan[gg]; scx[g] = d_gcx[gg]; scy[g] = d_gcy[gg];
        scl[g] = d_gcls[gg];
    }
    __syncthreads();
    int p = blockIdx.x * blockDim.x + threadIdx.x;
    if (p >= NP) return;

    float px1 = d_px1[p], py1 = d_py1[p], px2 = d_px2[p], py2 = d_py2[p];
    float parea = d_parea[p], patan = d_patan[p], pcx = d_pcx[p], pcy = d_pcy[p];

    for (int g = 0; g < gn; ++g) {
        float gx1 = sx1[g], gy1 = sy1[g], gx2 = sx2[g], gy2 = sy2[g];
        float ix1 = fmaxf(px1, gx1), iy1 = fmaxf(py1, gy1);
        float ix2 = fminf(px2, gx2), iy2 = fminf(py2, gy2);
        float inter = fmaxf(ix2 - ix1, 0.f) * fmaxf(iy2 - iy1, 0.f);
        float uni = parea + sar[g] - inter + EPSF;
        float iou = __fdividef(inter, uni);
        float dx = pcx - scx[g], dy = pcy - scy[g];
        float d2 = dx * dx + dy * dy;
        float cw = fmaxf(fmaxf(px2, gx2) - fminf(px1, gx1), EPSF);
        float ch = fmaxf(fmaxf(py2, gy2) - fminf(py1, gy1), EPSF);
        float c2 = cw * cw + ch * ch + EPSF;
        float dat = sat[g] - patan;
        float v = C_V * dat * dat;
        float alpha = __fdividef(v, 1.0f - iou + v + EPSF);
        float ciou = iou - __fdividef(d2, c2) - alpha * v;
        float cls = d_probT[(size_t)scl[g] * NP + p];
        float c = 0.75f * (1.0f - cls) + 1.0f * (1.0f - fminf(fmaxf(ciou, 0.f), 1.f));
        cost[(size_t)(g0 + g) * NP + p] = c;
    }
}

// ---------------- top-k phase 1: per-(row,chunk) exact top-10 ----------------
// key = (cost_bits<<32)|p  -> min-order == top_k(-cost) with jax tie-break.
__global__ void topk_phase1(const float* __restrict__ cost, int NP) {
    int g = blockIdx.y, ch = blockIdx.x;
    int chunk = (NP + gridDim.x - 1) / gridDim.x;
    int start = ch * chunk;
    int end = min(start + chunk, NP);
    const float* row = cost + (size_t)g * NP;

    unsigned long long t[10];
#pragma unroll
    for (int i = 0; i < 10; ++i) t[i] = ~0ULL;
    unsigned long long curmax = ~0ULL;

    for (int p = start + threadIdx.x; p < end; p += blockDim.x) {
        unsigned long long key =
            ((unsigned long long)__float_as_uint(row[p]) << 32) | (unsigned)p;
        top10_insert(t, curmax, key);
    }

    // warp-level extraction of warp top-10 (keys unique -> exactly one holder)
    __shared__ unsigned long long wout[4][10];
    int lane = threadIdx.x & 31, warp = threadIdx.x >> 5;
    for (int r = 0; r < 10; ++r) {
        unsigned long long mymin = top10_min(t);
        unsigned long long w = warp_min_u64(mymin);
        if (mymin == w) top10_kill(t, w);
        if (lane == 0) wout[warp][r] = w;
    }
    __syncthreads();

    // warp 0 merges 4x10 candidates -> chunk top-10
    if (warp == 0) {
        const unsigned long long* flat = &wout[0][0];
        unsigned long long c0 = flat[lane];
        unsigned long long c1 = (lane < 8) ? flat[32 + lane] : ~0ULL;
        if (c1 < c0) { unsigned long long tmp = c0; c0 = c1; c1 = tmp; }
        for (int r = 0; r < 10; ++r) {
            unsigned long long w = warp_min_u64(c0);
            if (c0 == w) { c0 = c1; c1 = ~0ULL; }
            if (lane == 0)
                d_cand[((size_t)g * gridDim.x + ch) * 10 + r] = w;
        }
    }
}

// ---------------- top-k phase 2: merge CH*10 candidates per row ----------------
__global__ void topk_phase2(float* __restrict__ out, int NP, int NG,
                            const int* __restrict__ epoch_p,
                            const int* __restrict__ tot_p) {
    int g = blockIdx.x;
    int lane = threadIdx.x;

    int ep = epoch_p[0];
    int te = tot_p[0];
    float tt = (float)ep / (float)max(1, te - 1);
    int K = (int)rintf(10.0f - 9.0f * tt);
    K = min(10, max(1, K));
    K = min(K, NP);

    unsigned long long t[10];
#pragma unroll
    for (int i = 0; i < 10; ++i) t[i] = ~0ULL;
    unsigned long long curmax = ~0ULL;

    const unsigned long long* cand = d_cand + (size_t)g * CH * 10;
    for (int i = lane; i < CH * 10; i += 32)
        top10_insert(t, curmax, cand[i]);

    for (int r = 0; r < K; ++r) {
        unsigned long long mymin = top10_min(t);
        unsigned long long w = warp_min_u64(mymin);
        if (mymin == w) top10_kill(t, w);
        if (lane == 0) {
            int p = (int)(unsigned)(w & 0xffffffffULL);
            size_t base = (size_t)NG * NP + 2 * ((size_t)g * K + r);
            out[base + 0] = (float)p;
            out[base + 1] = (float)g;
        }
    }
}

extern "C" void kernel_launch(void* const* d_in, const int* in_sizes, int n_in,
                              void* d_out, int out_size) {
    const float* preds      = (const float*)d_in[0];
    const float* gt_boxes   = (const float*)d_in[1];
    const int*   gt_classes = (const int*)d_in[2];
    const int*   epoch      = (const int*)d_in[3];
    const int*   tot        = (const int*)d_in[4];

    int NP = in_sizes[0] / (5 + NCC);
    int NG = in_sizes[2];
    float* out = (float*)d_out;

    prep_pred_kernel<<<(NP + 255) / 256, 256>>>(preds, NP);
    prep_gt_kernel<<<(NG + 255) / 256, 256>>>(gt_boxes, gt_classes, NG);
    sig_transpose_kernel<<<(NP + 63) / 64, 256>>>(preds, NP);

    dim3 cgrid((NP + 255) / 256, (NG + GSPAN - 1) / GSPAN);
    cost_kernel<<<cgrid, 256>>>(out, NP, NG);

    dim3 tgrid(CH, NG);
    topk_phase1<<<tgrid, 128>>>(out, NP);
    topk_phase2<<<NG, 32>>>(out, NP, NG, epoch, tot);
}

// round 6
// speedup vs baseline: 3.0825x; 2.1504x over previous
#include <cuda_runtime.h>
#include <cstdint>

#define NCC   80
#define NGMAX 300
#define NPMAX 100000
#define EPSF  1e-7f
#define C_V   0.4052847345693511f   // 4/pi^2
#define GSPAN 64                    // g-rows per cost block

// ---- scratch (static device arrays; 16B-aligned for float4 access) ----
__device__ __align__(16) float d_probT[(size_t)NCC * NPMAX];   // [class][pred]
__device__ __align__(16) float d_px1[NPMAX], d_py1[NPMAX], d_px2[NPMAX], d_py2[NPMAX];
__device__ __align__(16) float d_parea[NPMAX], d_patan[NPMAX], d_pcx[NPMAX], d_pcy[NPMAX];
__device__ float d_gx1[NGMAX], d_gy1[NGMAX], d_gx2[NGMAX], d_gy2[NGMAX];
__device__ float d_garea[NGMAX], d_gatan[NGMAX], d_gcx[NGMAX], d_gcy[NGMAX];
__device__ int   d_gcls[NGMAX];

__device__ __forceinline__ unsigned long long warp_min_u64(unsigned long long v) {
#pragma unroll
    for (int s = 16; s > 0; s >>= 1) {
        unsigned long long o = __shfl_xor_sync(0xffffffffu, v, s);
        v = o < v ? o : v;
    }
    return v;
}

// ============ kernel 1: all prep fused (one read of preds) ============
// 64 preds per block: sigmoid+transpose tile, box prep; block 0 also preps GTs.
__global__ void prep_all_kernel(const float* __restrict__ preds,
                                const float* __restrict__ gt_boxes,
                                const int* __restrict__ gt_classes,
                                int NP, int NG) {
    __shared__ float tile[64][NCC + 1];
    int p0 = blockIdx.x * 64;
    int nblk = min(64, NP - p0);

    // sigmoid load (coalesced along class dim)
    for (int i = threadIdx.x; i < 64 * NCC; i += blockDim.x) {
        int pp = i / NCC, cc = i - pp * NCC;
        float v = 0.f;
        if (pp < nblk) v = preds[(size_t)(p0 + pp) * (5 + NCC) + 5 + cc];
        tile[pp][cc] = 1.0f / (1.0f + __expf(-v));
    }

    // box prep: threads 0..63
    if (threadIdx.x < 64 && threadIdx.x < nblk) {
        int p = p0 + threadIdx.x;
        const float* r = preds + (size_t)p * (5 + NCC);
        float xc = r[0], yc = r[1], w = r[2], h = r[3];
        float x1 = xc - 0.5f * w, y1 = yc - 0.5f * h;
        float x2 = xc + 0.5f * w, y2 = yc + 0.5f * h;
        d_px1[p] = x1; d_py1[p] = y1; d_px2[p] = x2; d_py2[p] = y2;
        d_parea[p] = fmaxf(x2 - x1, 0.f) * fmaxf(y2 - y1, 0.f);
        float wp = fmaxf(x2 - x1, EPSF), hp = fmaxf(y2 - y1, EPSF);
        d_patan[p] = atanf(wp / hp);
        d_pcx[p] = 0.5f * (x1 + x2);
        d_pcy[p] = 0.5f * (y1 + y2);
    }

    // GT prep: block 0 only
    if (blockIdx.x == 0) {
        for (int g = threadIdx.x; g < NG; g += blockDim.x) {
            float x1 = gt_boxes[g * 4 + 0], y1 = gt_boxes[g * 4 + 1];
            float x2 = gt_boxes[g * 4 + 2], y2 = gt_boxes[g * 4 + 3];
            d_gx1[g] = x1; d_gy1[g] = y1; d_gx2[g] = x2; d_gy2[g] = y2;
            d_garea[g] = fmaxf(x2 - x1, 0.f) * fmaxf(y2 - y1, 0.f);
            float wg = fmaxf(x2 - x1, EPSF), hg = fmaxf(y2 - y1, EPSF);
            d_gatan[g] = atanf(wg / hg);
            d_gcx[g] = 0.5f * (x1 + x2);
            d_gcy[g] = 0.5f * (y1 + y2);
            d_gcls[g] = gt_classes[g];
        }
    }
    __syncthreads();

    // transposed store (coalesced along pred dim)
    for (int i = threadIdx.x; i < NCC * 64; i += blockDim.x) {
        int cc = i / 64, pp = i - cc * 64;
        if (pp < nblk)
            d_probT[(size_t)cc * NP + p0 + pp] = tile[pp][cc];
    }
}

// ============ kernel 2: cost matrix, 4 preds/thread ============
__global__ void cost_kernel(float* __restrict__ cost, int NP, int NG) {
    __shared__ float sx1[GSPAN], sy1[GSPAN], sx2[GSPAN], sy2[GSPAN];
    __shared__ float sar[GSPAN], sat[GSPAN], scx[GSPAN], scy[GSPAN];
    __shared__ const float4* sprob[GSPAN];
    int g0 = blockIdx.y * GSPAN;
    int gn = min(GSPAN, NG - g0);
    for (int g = threadIdx.x; g < gn; g += blockDim.x) {
        int gg = g0 + g;
        sx1[g] = d_gx1[gg]; sy1[g] = d_gy1[gg]; sx2[g] = d_gx2[gg]; sy2[g] = d_gy2[gg];
        sar[g] = d_garea[gg]; sat[g] = d_gatan[gg]; scx[g] = d_gcx[gg]; scy[g] = d_gcy[gg];
        sprob[g] = (const float4*)(d_probT + (size_t)d_gcls[gg] * NP);
    }
    __syncthreads();

    int q = blockIdx.x * blockDim.x + threadIdx.x;   // float4 index
    int n4 = NP >> 2;
    if (q >= n4) return;

    float4 px1 = ((const float4*)d_px1)[q], py1 = ((const float4*)d_py1)[q];
    float4 px2 = ((const float4*)d_px2)[q], py2 = ((const float4*)d_py2)[q];
    float4 par = ((const float4*)d_parea)[q], pat = ((const float4*)d_patan)[q];
    float4 pcx = ((const float4*)d_pcx)[q], pcy = ((const float4*)d_pcy)[q];

    float4* crow = (float4*)(cost + (size_t)g0 * NP) + q;

    for (int g = 0; g < gn; ++g) {
        float gx1 = sx1[g], gy1 = sy1[g], gx2 = sx2[g], gy2 = sy2[g];
        float gar = sar[g], gat = sat[g], gcx = scx[g], gcy = scy[g];
        float4 cp = sprob[g][q];
        float4 out;
        const float* PX1 = &px1.x; const float* PY1 = &py1.x;
        const float* PX2 = &px2.x; const float* PY2 = &py2.x;
        const float* PAR = &par.x; const float* PAT = &pat.x;
        const float* PCX = &pcx.x; const float* PCY = &pcy.x;
        const float* CP  = &cp.x;  float* OUT = &out.x;
#pragma unroll
        for (int j = 0; j < 4; ++j) {
            float ix1 = fmaxf(PX1[j], gx1), iy1 = fmaxf(PY1[j], gy1);
            float ix2 = fminf(PX2[j], gx2), iy2 = fminf(PY2[j], gy2);
            float inter = fmaxf(ix2 - ix1, 0.f) * fmaxf(iy2 - iy1, 0.f);
            float uni = PAR[j] + gar - inter + EPSF;
            float iou = __fdividef(inter, uni);
            float dx = PCX[j] - gcx, dy = PCY[j] - gcy;
            float d2 = dx * dx + dy * dy;
            float cw = fmaxf(fmaxf(PX2[j], gx2) - fminf(PX1[j], gx1), EPSF);
            float ch = fmaxf(fmaxf(PY2[j], gy2) - fminf(PY1[j], gy1), EPSF);
            float c2 = cw * cw + ch * ch + EPSF;
            float dat = gat - PAT[j];
            float v = C_V * dat * dat;
            float alpha = __fdividef(v, 1.0f - iou + v + EPSF);
            float ciou = iou - __fdividef(d2, c2) - alpha * v;
            OUT[j] = 0.75f * (1.0f - CP[j]) + (1.0f - fminf(fmaxf(ciou, 0.f), 1.f));
        }
        *crow = out;
        crow += n4;
    }
}

// ============ kernel 3: exact top-K per row, min-extraction ============
// key = (cost_bits<<32)|p : min-order == top_k(-cost) with jax tie-break.
// Branch-free chunk-min scan, then K rounds: block-min -> winner rescans its
// chunk with key > win (extraction keys strictly increase, so no bookkeeping).
#define TKB 1024
__global__ void topk_row_kernel(const float* __restrict__ cost,
                                float* __restrict__ out, int NP, int NG,
                                const int* __restrict__ epoch_p,
                                const int* __restrict__ tot_p) {
    int g = blockIdx.x;
    int t = threadIdx.x;
    int lane = t & 31, wid = t >> 5;
    int n4 = NP >> 2;

    int ep = epoch_p[0];
    int te = tot_p[0];
    float tt = (float)ep / (float)max(1, te - 1);
    int K = (int)rintf(10.0f - 9.0f * tt);
    K = min(10, max(1, K));
    K = min(K, NP);

    const float4* row4 = (const float4*)(cost + (size_t)g * NP);

    // branch-free chunk min (full MLP)
    unsigned long long mycur = ~0ULL;
    for (int i = t; i < n4; i += TKB) {
        float4 v = row4[i];
        int p = i << 2;
        unsigned long long k0 = ((unsigned long long)__float_as_uint(v.x) << 32) | (unsigned)(p);
        unsigned long long k1 = ((unsigned long long)__float_as_uint(v.y) << 32) | (unsigned)(p + 1);
        unsigned long long k2 = ((unsigned long long)__float_as_uint(v.z) << 32) | (unsigned)(p + 2);
        unsigned long long k3 = ((unsigned long long)__float_as_uint(v.w) << 32) | (unsigned)(p + 3);
        unsigned long long a = k0 < k1 ? k0 : k1;
        unsigned long long b = k2 < k3 ? k2 : k3;
        a = a < b ? a : b;
        mycur = a < mycur ? a : mycur;
    }
    // scalar tail (NP not multiple of 4)
    for (int p = (n4 << 2) + t; p < NP; p += TKB) {
        unsigned long long k =
            ((unsigned long long)__float_as_uint(cost[(size_t)g * NP + p]) << 32) | (unsigned)p;
        mycur = k < mycur ? k : mycur;
    }

    __shared__ unsigned long long s_warp[TKB / 32];
    __shared__ unsigned long long s_win;

    for (int r = 0; r < K; ++r) {
        unsigned long long w = warp_min_u64(mycur);
        if (lane == 0) s_warp[wid] = w;
        __syncthreads();
        if (wid == 0) {
            unsigned long long v = s_warp[lane];
            v = warp_min_u64(v);
            if (lane == 0) s_win = v;
        }
        __syncthreads();
        unsigned long long win = s_win;
        if (t == 0) {
            int p = (int)(unsigned)(win & 0xffffffffULL);
            size_t base = (size_t)NG * NP + 2 * ((size_t)g * K + r);
            out[base + 0] = (float)p;
            out[base + 1] = (float)g;
        }
        if (mycur == win) {   // unique winner rescans its chunk (L2-hot)
            unsigned long long nm = ~0ULL;
            for (int i = t; i < n4; i += TKB) {
                float4 v = row4[i];
                int p = i << 2;
                unsigned long long k0 = ((unsigned long long)__float_as_uint(v.x) << 32) | (unsigned)(p);
                unsigned long long k1 = ((unsigned long long)__float_as_uint(v.y) << 32) | (unsigned)(p + 1);
                unsigned long long k2 = ((unsigned long long)__float_as_uint(v.z) << 32) | (unsigned)(p + 2);
                unsigned long long k3 = ((unsigned long long)__float_as_uint(v.w) << 32) | (unsigned)(p + 3);
                if (k0 > win && k0 < nm) nm = k0;
                if (k1 > win && k1 < nm) nm = k1;
                if (k2 > win && k2 < nm) nm = k2;
                if (k3 > win && k3 < nm) nm = k3;
            }
            for (int p = (n4 << 2) + t; p < NP; p += TKB) {
                unsigned long long k =
                    ((unsigned long long)__float_as_uint(cost[(size_t)g * NP + p]) << 32) | (unsigned)p;
                if (k > win && k < nm) nm = k;
            }
            mycur = nm;
        }
        __syncthreads();
    }
}

extern "C" void kernel_launch(void* const* d_in, const int* in_sizes, int n_in,
                              void* d_out, int out_size) {
    const float* preds      = (const float*)d_in[0];
    const float* gt_boxes   = (const float*)d_in[1];
    const int*   gt_classes = (const int*)d_in[2];
    const int*   epoch      = (const int*)d_in[3];
    const int*   tot        = (const int*)d_in[4];

    int NP = in_sizes[0] / (5 + NCC);
    int NG = in_sizes[2];
    float* out = (float*)d_out;

    prep_all_kernel<<<(NP + 63) / 64, 256>>>(preds, gt_boxes, gt_classes, NP, NG);

    int n4 = NP >> 2;
    dim3 cgrid((n4 + 255) / 256, (NG + GSPAN - 1) / GSPAN);
    cost_kernel<<<cgrid, 256>>>(out, NP, NG);

    topk_row_kernel<<<NG, TKB>>>(out, out, NP, NG, epoch, tot);
}

// round 7
// speedup vs baseline: 3.8641x; 1.2536x over previous
#include <cuda_runtime.h>
#include <cstdint>

#define NCC   80
#define NGMAX 300
#define NPMAX 100000
#define EPSF  1e-7f
#define C_V   0.4052847345693511f   // 4/pi^2
#define NB    148                   // blocks (<= SM count, co-resident)
#define NT    1024                  // threads per block
#define GCH   32                    // g-rows per cost unit
#define QCH   1024                  // float4 columns per cost unit

// ---- scratch (static device arrays; 16B-aligned for float4 access) ----
__device__ __align__(16) float d_probT[(size_t)NCC * NPMAX];   // [class][pred]
__device__ __align__(16) float d_px1[NPMAX], d_py1[NPMAX], d_px2[NPMAX], d_py2[NPMAX];
__device__ __align__(16) float d_parea[NPMAX], d_patan[NPMAX], d_pcx[NPMAX], d_pcy[NPMAX];
__device__ float d_gx1[NGMAX], d_gy1[NGMAX], d_gx2[NGMAX], d_gy2[NGMAX];
__device__ float d_garea[NGMAX], d_gatan[NGMAX], d_gcx[NGMAX], d_gcy[NGMAX];
__device__ int   d_gcls[NGMAX];

// barrier + work counters
__device__ unsigned d_bar_count = 0;
__device__ unsigned d_bar_gen   = 0;
__device__ unsigned d_unit_ctr  = 0;
__device__ unsigned d_row_ctr   = 0;

__device__ __forceinline__ void grid_sync() {
    __syncthreads();
    __threadfence();
    if (threadIdx.x == 0) {
        unsigned gen = *((volatile unsigned*)&d_bar_gen);
        unsigned t = atomicAdd(&d_bar_count, 1u);
        if (t == NB - 1) {
            d_bar_count = 0;
            __threadfence();
            atomicAdd(&d_bar_gen, 1u);
        } else {
            while (*((volatile unsigned*)&d_bar_gen) == gen) { __nanosleep(64); }
        }
    }
    __threadfence();
    __syncthreads();
}

__device__ __forceinline__ unsigned long long warp_min_u64(unsigned long long v) {
#pragma unroll
    for (int s = 16; s > 0; s >>= 1) {
        unsigned long long o = __shfl_xor_sync(0xffffffffu, v, s);
        v = o < v ? o : v;
    }
    return v;
}

__device__ __forceinline__ unsigned long long u64min(unsigned long long a, unsigned long long b) {
    return a < b ? a : b;
}
__device__ __forceinline__ unsigned long long u64max(unsigned long long a, unsigned long long b) {
    return a > b ? a : b;
}

__global__ __launch_bounds__(NT, 1)
void fused_kernel(const float* __restrict__ preds,
                  const float* __restrict__ gt_boxes,
                  const int* __restrict__ gt_classes,
                  const int* __restrict__ epoch_p,
                  const int* __restrict__ tot_p,
                  float* __restrict__ out,
                  int NP, int NG) {
    __shared__ float s_tile[128][NCC + 1];              // 41.4 KB (stage A)
    __shared__ float sgx1[GCH], sgy1[GCH], sgx2[GCH], sgy2[GCH];
    __shared__ float sgar[GCH], sgat[GCH], sgcx[GCH], sgcy[GCH];
    __shared__ const float4* sprob[GCH];
    __shared__ unsigned s_u, s_row;
    __shared__ unsigned long long s_warp[NT / 32];
    __shared__ unsigned long long s_win;

    int tid = threadIdx.x;
    int bid = blockIdx.x;
    int lane = tid & 31, wid = tid >> 5;
    int n4 = NP >> 2;
    float* cost = out;

    // ================= stage A: prep =================
    if (bid == 0) {
        for (int g = tid; g < NG; g += NT) {
            float x1 = gt_boxes[g * 4 + 0], y1 = gt_boxes[g * 4 + 1];
            float x2 = gt_boxes[g * 4 + 2], y2 = gt_boxes[g * 4 + 3];
            d_gx1[g] = x1; d_gy1[g] = y1; d_gx2[g] = x2; d_gy2[g] = y2;
            d_garea[g] = fmaxf(x2 - x1, 0.f) * fmaxf(y2 - y1, 0.f);
            float wg = fmaxf(x2 - x1, EPSF), hg = fmaxf(y2 - y1, EPSF);
            d_gatan[g] = atanf(wg / hg);
            d_gcx[g] = 0.5f * (x1 + x2);
            d_gcy[g] = 0.5f * (y1 + y2);
            d_gcls[g] = gt_classes[g];
        }
        if (tid == 0) { d_unit_ctr = 0; d_row_ctr = 0; }
    }

    int ntiles = (NP + 127) >> 7;
    for (int tile = bid; tile < ntiles; tile += NB) {
        int p0 = tile << 7;
        int nblk = min(128, NP - p0);
        __syncthreads();   // protect s_tile reuse
        for (int i = tid; i < 128 * NCC; i += NT) {
            int pp = i / NCC, cc = i - pp * NCC;
            float v = 0.f;
            if (pp < nblk) v = preds[(size_t)(p0 + pp) * (5 + NCC) + 5 + cc];
            s_tile[pp][cc] = 1.0f / (1.0f + __expf(-v));
        }
        if (tid < nblk) {
            int p = p0 + tid;
            const float* r = preds + (size_t)p * (5 + NCC);
            float xc = r[0], yc = r[1], w = r[2], h = r[3];
            float x1 = xc - 0.5f * w, y1 = yc - 0.5f * h;
            float x2 = xc + 0.5f * w, y2 = yc + 0.5f * h;
            d_px1[p] = x1; d_py1[p] = y1; d_px2[p] = x2; d_py2[p] = y2;
            d_parea[p] = fmaxf(x2 - x1, 0.f) * fmaxf(y2 - y1, 0.f);
            float wp = fmaxf(x2 - x1, EPSF), hp = fmaxf(y2 - y1, EPSF);
            d_patan[p] = atanf(wp / hp);
            d_pcx[p] = 0.5f * (x1 + x2);
            d_pcy[p] = 0.5f * (y1 + y2);
        }
        __syncthreads();
        for (int i = tid; i < NCC * 128; i += NT) {
            int cc = i >> 7, pp = i & 127;
            if (pp < nblk)
                d_probT[(size_t)cc * NP + p0 + pp] = s_tile[pp][cc];
        }
    }

    grid_sync();

    // ================= stage B: cost matrix =================
    int nq = (n4 + QCH - 1) / QCH;
    int ngc = (NG + GCH - 1) / GCH;
    unsigned nunits = (unsigned)(nq * ngc);
    for (;;) {
        __syncthreads();   // protect sg* reuse + s_u
        if (tid == 0) s_u = atomicAdd(&d_unit_ctr, 1u);
        __syncthreads();
        unsigned u = s_u;
        if (u >= nunits) break;
        int qc = (int)(u % (unsigned)nq);
        int gc = (int)(u / (unsigned)nq);
        int g0 = gc * GCH;
        int gn = min(GCH, NG - g0);
        if (tid < gn) {
            int gg = g0 + tid;
            sgx1[tid] = d_gx1[gg]; sgy1[tid] = d_gy1[gg];
            sgx2[tid] = d_gx2[gg]; sgy2[tid] = d_gy2[gg];
            sgar[tid] = d_garea[gg]; sgat[tid] = d_gatan[gg];
            sgcx[tid] = d_gcx[gg]; sgcy[tid] = d_gcy[gg];
            sprob[tid] = (const float4*)(d_probT + (size_t)d_gcls[gg] * NP);
        }
        __syncthreads();

        int q = qc * QCH + tid;
        if (q < n4) {
            float4 px1 = ((const float4*)d_px1)[q], py1 = ((const float4*)d_py1)[q];
            float4 px2 = ((const float4*)d_px2)[q], py2 = ((const float4*)d_py2)[q];
            float4 par = ((const float4*)d_parea)[q], pat = ((const float4*)d_patan)[q];
            float4 pcx = ((const float4*)d_pcx)[q], pcy = ((const float4*)d_pcy)[q];
            float4* crow = (float4*)(cost + (size_t)g0 * NP) + q;
            for (int g = 0; g < gn; ++g) {
                float gx1 = sgx1[g], gy1 = sgy1[g], gx2 = sgx2[g], gy2 = sgy2[g];
                float gar = sgar[g], gat = sgat[g], gcx = sgcx[g], gcy = sgcy[g];
                float4 cp = sprob[g][q];
                float4 o;
                const float* PX1 = &px1.x; const float* PY1 = &py1.x;
                const float* PX2 = &px2.x; const float* PY2 = &py2.x;
                const float* PAR = &par.x; const float* PAT = &pat.x;
                const float* PCX = &pcx.x; const float* PCY = &pcy.x;
                const float* CP = &cp.x; float* OUT = &o.x;
#pragma unroll
                for (int j = 0; j < 4; ++j) {
                    float ix1 = fmaxf(PX1[j], gx1), iy1 = fmaxf(PY1[j], gy1);
                    float ix2 = fminf(PX2[j], gx2), iy2 = fminf(PY2[j], gy2);
                    float inter = fmaxf(ix2 - ix1, 0.f) * fmaxf(iy2 - iy1, 0.f);
                    float uni = PAR[j] + gar - inter + EPSF;
                    float iou = __fdividef(inter, uni);
                    float dx = PCX[j] - gcx, dy = PCY[j] - gcy;
                    float d2 = dx * dx + dy * dy;
                    float cw = fmaxf(fmaxf(PX2[j], gx2) - fminf(PX1[j], gx1), EPSF);
                    float ch = fmaxf(fmaxf(PY2[j], gy2) - fminf(PY1[j], gy1), EPSF);
                    float c2 = cw * cw + ch * ch + EPSF;
                    float dat = gat - PAT[j];
                    float v = C_V * dat * dat;
                    float alpha = __fdividef(v, 1.0f - iou + v + EPSF);
                    float ciou = iou - __fdividef(d2, c2) - alpha * v;
                    OUT[j] = 0.75f * (1.0f - CP[j]) + (1.0f - fminf(fmaxf(ciou, 0.f), 1.f));
                }
                *crow = o;
                crow += n4;
            }
        }
    }

    grid_sync();

    // ================= stage C: per-row exact top-K =================
    int ep = epoch_p[0];
    int te = tot_p[0];
    float tt = (float)ep / (float)max(1, te - 1);
    int K = (int)rintf(10.0f - 9.0f * tt);
    K = min(10, max(1, K));
    K = min(K, NP);

    for (;;) {
        __syncthreads();   // protect s_row / s_warp reuse
        if (tid == 0) s_row = atomicAdd(&d_row_ctr, 1u);
        __syncthreads();
        unsigned g = s_row;
        if (g >= (unsigned)NG) break;

        const float4* row4 = (const float4*)(cost + (size_t)g * NP);

        // branch-free per-thread top-2 of the strided chunk
        unsigned long long m1 = ~0ULL, m2 = ~0ULL;
        for (int i = tid; i < n4; i += NT) {
            float4 v = row4[i];
            int p = i << 2;
            unsigned long long k0 = ((unsigned long long)__float_as_uint(v.x) << 32) | (unsigned)(p);
            unsigned long long k1 = ((unsigned long long)__float_as_uint(v.y) << 32) | (unsigned)(p + 1);
            unsigned long long k2 = ((unsigned long long)__float_as_uint(v.z) << 32) | (unsigned)(p + 2);
            unsigned long long k3 = ((unsigned long long)__float_as_uint(v.w) << 32) | (unsigned)(p + 3);
            m2 = u64min(m2, u64max(m1, k0)); m1 = u64min(m1, k0);
            m2 = u64min(m2, u64max(m1, k1)); m1 = u64min(m1, k1);
            m2 = u64min(m2, u64max(m1, k2)); m1 = u64min(m1, k2);
            m2 = u64min(m2, u64max(m1, k3)); m1 = u64min(m1, k3);
        }
        for (int p = (n4 << 2) + tid; p < NP; p += NT) {
            unsigned long long k =
                ((unsigned long long)__float_as_uint(cost[(size_t)g * NP + p]) << 32) | (unsigned)p;
            m2 = u64min(m2, u64max(m1, k)); m1 = u64min(m1, k);
        }

        for (int r = 0; r < K; ++r) {
            unsigned long long w = warp_min_u64(m1);
            if (lane == 0) s_warp[wid] = w;
            __syncthreads();
            if (wid == 0) {
                unsigned long long v = s_warp[lane];
                v = warp_min_u64(v);
                if (lane == 0) s_win = v;
            }
            __syncthreads();
            unsigned long long win = s_win;
            if (tid == 0) {
                int p = (int)(unsigned)(win & 0xffffffffULL);
                size_t base = (size_t)NG * NP + 2 * ((size_t)g * K + r);
                out[base + 0] = (float)p;
                out[base + 1] = (float)g;
            }
            if (m1 == win) {
                if (m2 != ~0ULL) {
                    m1 = m2; m2 = ~0ULL;
                } else {
                    // rare: this thread won twice -> rescan chunk for keys > win
                    unsigned long long a1 = ~0ULL, a2 = ~0ULL;
                    for (int i = tid; i < n4; i += NT) {
                        float4 v = row4[i];
                        int p = i << 2;
                        unsigned long long kk[4];
                        kk[0] = ((unsigned long long)__float_as_uint(v.x) << 32) | (unsigned)(p);
                        kk[1] = ((unsigned long long)__float_as_uint(v.y) << 32) | (unsigned)(p + 1);
                        kk[2] = ((unsigned long long)__float_as_uint(v.z) << 32) | (unsigned)(p + 2);
                        kk[3] = ((unsigned long long)__float_as_uint(v.w) << 32) | (unsigned)(p + 3);
#pragma unroll
                        for (int j = 0; j < 4; ++j) {
                            unsigned long long k = kk[j];
                            if (k > win) { a2 = u64min(a2, u64max(a1, k)); a1 = u64min(a1, k); }
                        }
                    }
                    for (int p = (n4 << 2) + tid; p < NP; p += NT) {
                        unsigned long long k =
                            ((unsigned long long)__float_as_uint(cost[(size_t)g * NP + p]) << 32) | (unsigned)p;
                        if (k > win) { a2 = u64min(a2, u64max(a1, k)); a1 = u64min(a1, k); }
                    }
                    m1 = a1; m2 = a2;
                }
            }
            __syncthreads();
        }
    }
}

extern "C" void kernel_launch(void* const* d_in, const int* in_sizes, int n_in,
                              void* d_out, int out_size) {
    const float* preds      = (const float*)d_in[0];
    const float* gt_boxes   = (const float*)d_in[1];
    const int*   gt_classes = (const int*)d_in[2];
    const int*   epoch      = (const int*)d_in[3];
    const int*   tot        = (const int*)d_in[4];

    int NP = in_sizes[0] / (5 + NCC);
    int NG = in_sizes[2];
    float* out = (float*)d_out;

    fused_kernel<<<NB, NT>>>(preds, gt_boxes, gt_classes, epoch, tot, out, NP, NG);
}